// round 15
// baseline (speedup 1.0000x reference)
#include <cuda_runtime.h>
#include <cuda_fp16.h>
#include <cuda_bf16.h>
#include <cstdint>
#include <cstddef>

// ---------------- problem constants ----------------
#define NNODE   650
#define NATTR   250
#define NOBJ    400
#define NEDGE   100000
#define NPAIR   100000      // 250*400
#define D_IN    512
#define D_HID   4096
#define D_NODE  512
#define D_P1    1200
#define EMB     800
#define FEAT    2048
#define BIMG    256
#define LN_EPS  1e-5f

// ---------------- device scratch (static; no runtime alloc) ----------------
__device__ float g_aggM[NNODE * D_HID];
__device__ float g_h[NNODE * D_HID];
__device__ float g_outn[NNODE * D_NODE];
__device__ float g_A[NATTR * D_P1];
__device__ float g_O[NOBJ * D_P1];
__device__ __half g_Ah[NATTR * D_P1];
__device__ __half g_Oh[NOBJ * D_P1];
__device__ __half g_Wh[EMB * D_P1];
__device__ float g_img1[BIMG * 768];
__device__ float g_img2[BIMG * 1000];
__device__ float g_i3[BIMG * EMB];
__device__ float g_ig[BIMG * EMB];
__device__ float g_Sb[BIMG];
__device__ float g_cb[BIMG];
__device__ __half g_qh[NPAIR * EMB];          // 160 MB pair pre-LN activations (half)
__device__ float g_mean[NPAIR];
__device__ float g_rstd[NPAIR];
__device__ float g_deginv[NNODE];
__device__ int   g_cnt[NNODE];
__device__ int   g_offs[NNODE + 1];
__device__ int   g_cursor[NNODE];
__device__ int   g_csr[NEDGE];

// ---------------- fp16 mma / ldmatrix helpers ----------------
// D(16x8,f32) += A(16x16,f16,row) * B(16x8,f16,col)
__device__ __forceinline__ void mma_f16(float* c, const unsigned* a, const unsigned* b) {
    asm volatile(
        "mma.sync.aligned.m16n8k16.row.col.f32.f16.f16.f32 "
        "{%0,%1,%2,%3}, {%4,%5,%6,%7}, {%8,%9}, {%0,%1,%2,%3};"
        : "+f"(c[0]), "+f"(c[1]), "+f"(c[2]), "+f"(c[3])
        : "r"(a[0]), "r"(a[1]), "r"(a[2]), "r"(a[3]), "r"(b[0]), "r"(b[1]));
}

__device__ __forceinline__ void ldsm_x4(unsigned& r0, unsigned& r1, unsigned& r2, unsigned& r3,
                                        uint32_t addr) {
    asm volatile("ldmatrix.sync.aligned.m8n8.x4.shared.b16 {%0,%1,%2,%3}, [%4];"
                 : "=r"(r0), "=r"(r1), "=r"(r2), "=r"(r3) : "r"(addr));
}
__device__ __forceinline__ void ldsm_x2(unsigned& r0, unsigned& r1, uint32_t addr) {
    asm volatile("ldmatrix.sync.aligned.m8n8.x2.shared.b16 {%0,%1}, [%2];"
                 : "=r"(r0), "=r"(r1) : "r"(addr));
}

// ---------------- fp32 -> fp16 convert ----------------
__global__ void k_cvt_half(const float* __restrict__ src, __half* __restrict__ dst, int n4) {
    int i = blockIdx.x * blockDim.x + threadIdx.x;
    if (i < n4) {
        float4 v = ((const float4*)src)[i];
        ((__half2*)dst)[2 * i]     = __floats2half2_rn(v.x, v.y);
        ((__half2*)dst)[2 * i + 1] = __floats2half2_rn(v.z, v.w);
    }
}

// ---------------- CSR build ----------------
__global__ void k_zero_cnt() {
    int t = blockIdx.x * blockDim.x + threadIdx.x;
    if (t < NNODE) g_cnt[t] = 0;
}

__global__ void k_count(const int* __restrict__ dst) {
    int e = blockIdx.x * blockDim.x + threadIdx.x;
    if (e < NEDGE) atomicAdd(&g_cnt[dst[e]], 1);
}

__global__ void k_scan() {
    __shared__ int s[NNODE + 1];
    int t = threadIdx.x;                 // 1024 threads
    if (t < NNODE) s[t + 1] = g_cnt[t];
    if (t == 0) s[0] = 0;
    __syncthreads();
    for (int d = 1; d < NNODE + 1; d <<= 1) {
        int v = 0;
        if (t < NNODE + 1 && t >= d) v = s[t - d];
        __syncthreads();
        if (t < NNODE + 1 && t >= d) s[t] += v;
        __syncthreads();
    }
    if (t < NNODE + 1) g_offs[t] = s[t];
    if (t < NNODE) {
        g_cursor[t] = s[t];
        g_deginv[t] = 1.0f / fmaxf((float)g_cnt[t], 1.0f);
    }
}

__global__ void k_fill(const int* __restrict__ src, const int* __restrict__ dst) {
    int e = blockIdx.x * blockDim.x + threadIdx.x;
    if (e < NEDGE) {
        int p = atomicAdd(&g_cursor[dst[e]], 1);
        g_csr[p] = src[e];
    }
}

// ---------------- segment mean via CSR gather ----------------
__global__ void k_gather(const float* __restrict__ X, float* __restrict__ out, int D) {
    int n = blockIdx.x;
    int f = blockIdx.y * 256 + threadIdx.x;
    int beg = g_offs[n], end = g_offs[n + 1];
    float inv = g_deginv[n];
    float a0 = 0.f, a1 = 0.f, a2 = 0.f, a3 = 0.f;
    int e = beg;
    for (; e + 4 <= end; e += 4) {
        int s0 = g_csr[e], s1 = g_csr[e + 1], s2 = g_csr[e + 2], s3 = g_csr[e + 3];
        a0 += X[(size_t)s0 * D + f];
        a1 += X[(size_t)s1 * D + f];
        a2 += X[(size_t)s2 * D + f];
        a3 += X[(size_t)s3 * D + f];
    }
    for (; e < end; e++) a0 += X[(size_t)g_csr[e] * D + f];
    out[(size_t)n * D + f] = (a0 + a1 + a2 + a3) * inv;
}

// ---------------- generic small GEMM: C = act(A@B^T (+ A2@B2^T) + bias) ----------------
template<bool RELU, bool DUAL>
__global__ void __launch_bounds__(256) gemm64(
    const float* __restrict__ A, int lda, const float* __restrict__ B, int ldb, int K,
    const float* __restrict__ A2, int lda2, const float* __restrict__ B2, int ldb2, int K2,
    const float* __restrict__ bias, float* __restrict__ C, int ldc, int M, int N)
{
    __shared__ float As[8][65];
    __shared__ float Bs[8][65];
    const int t = threadIdx.x;
    const int m0 = blockIdx.y * 64, n0 = blockIdx.x * 64;
    const int tx = t & 15, ty = t >> 4;
    float acc[4][4];
#pragma unroll
    for (int i = 0; i < 4; i++)
#pragma unroll
        for (int j = 0; j < 4; j++) acc[i][j] = 0.f;

    const int npass = DUAL ? 2 : 1;
    for (int pass = 0; pass < npass; pass++) {
        const float* Ap = pass ? A2 : A;
        const float* Bp = pass ? B2 : B;
        const int ldap = pass ? lda2 : lda;
        const int ldbp = pass ? ldb2 : ldb;
        const int Kp = pass ? K2 : K;
        for (int k0 = 0; k0 < Kp; k0 += 8) {
            __syncthreads();
#pragma unroll
            for (int s = 0; s < 2; s++) {
                int id = t + s * 256;
                int m = id >> 3, k = id & 7;
                As[k][m] = (m0 + m < M) ? Ap[(size_t)(m0 + m) * ldap + k0 + k] : 0.f;
                Bs[k][m] = (n0 + m < N) ? Bp[(size_t)(n0 + m) * ldbp + k0 + k] : 0.f;
            }
            __syncthreads();
#pragma unroll
            for (int kk = 0; kk < 8; kk++) {
                float a[4], b[4];
#pragma unroll
                for (int i = 0; i < 4; i++) a[i] = As[kk][ty * 4 + i];
#pragma unroll
                for (int j = 0; j < 4; j++) b[j] = Bs[kk][tx * 4 + j];
#pragma unroll
                for (int i = 0; i < 4; i++)
#pragma unroll
                    for (int j = 0; j < 4; j++)
                        acc[i][j] = fmaf(a[i], b[j], acc[i][j]);
            }
        }
    }
#pragma unroll
    for (int i = 0; i < 4; i++) {
        int m = m0 + ty * 4 + i;
        if (m >= M) continue;
#pragma unroll
        for (int j = 0; j < 4; j++) {
            int n = n0 + tx * 4 + j;
            if (n >= N) continue;
            float v = acc[i][j] + (bias ? bias[n] : 0.f);
            if (RELU) v = fmaxf(v, 0.f);
            C[(size_t)m * ldc + n] = v;
        }
    }
}

// ---------------- big pair GEMM (fp16 m16n8k16 + ldmatrix, half sources) ---------------
// q[p,n] = relu(A[i(p)]+O[j(p)]) @ Wp2^T + bp2, all operands pre-converted to half.
// BM=128, BN=80, BK=48 halves. 8 warps: warp grid 4(m) x 2(n), warp tile 32x40.
// Smem [row][k] __half pitch 56 (112 B): ldmatrix row offsets cover all banks.
#define PG_KH 56   // 48 + 8 pad (halves)
__global__ void __launch_bounds__(256, 2) pair_gemm(const float* __restrict__ bias)
{
    __shared__ __align__(16) __half As[128][PG_KH];
    __shared__ __align__(16) __half Bs[80][PG_KH];
    __shared__ int arow[128];
    __shared__ int orow[128];
    const int t = threadIdx.x;
    const int m0 = blockIdx.y * 128;
    const int n0 = blockIdx.x * 80;
    if (t < 128) {
        int p = m0 + t;
        if (p > NPAIR - 1) p = NPAIR - 1;
        int ii = p / NOBJ;
        arow[t] = ii * D_P1;
        orow[t] = (p - ii * NOBJ) * D_P1;
    }
    const int wid = t >> 5, lane = t & 31;
    const int wm = wid & 3;          // rows wm*32
    const int wn = wid >> 2;         // cols wn*40
    const int gid = lane >> 2, tig = lane & 3;

    const uint32_t smA = (uint32_t)__cvta_generic_to_shared(&As[0][0]);
    const uint32_t smB = (uint32_t)__cvta_generic_to_shared(&Bs[0][0]);
    const uint32_t offA = smA + (uint32_t)((((lane & 7) + ((lane >> 3) & 1) * 8) * PG_KH) * 2
                                           + ((lane >> 4) & 1) * 16);
    const uint32_t offB4 = smB + (uint32_t)((((lane & 7) + (lane >> 4) * 8) * PG_KH) * 2
                                            + ((lane >> 3) & 1) * 16);
    const uint32_t offB2 = smB + (uint32_t)(((lane & 7) * PG_KH) * 2
                                            + ((lane >> 3) & 1) * 16);

    float acc[2][5][4];
#pragma unroll
    for (int mt = 0; mt < 2; mt++)
#pragma unroll
        for (int nt = 0; nt < 5; nt++)
#pragma unroll
            for (int r = 0; r < 4; r++) acc[mt][nt][r] = 0.f;

    const __half2 hz = __float2half2_rn(0.f);

    for (int k0 = 0; k0 < D_P1; k0 += 48) {
        __syncthreads();
        // fill As: 128 rows x 6 16B-chunks (8 halves) = 768, 3 per thread.
        // relu(A+O) computed in half2 (inputs already half-rounded).
#pragma unroll
        for (int s = 0; s < 3; s++) {
            int id = t + s * 256;
            int m = id / 6, c8 = id % 6;
            const uint4 av = *(const uint4*)(g_Ah + arow[m] + k0 + c8 * 8);
            const uint4 ov = *(const uint4*)(g_Oh + orow[m] + k0 + c8 * 8);
            uint4 r;
            *(__half2*)&r.x = __hmax2(__hadd2(*(const __half2*)&av.x, *(const __half2*)&ov.x), hz);
            *(__half2*)&r.y = __hmax2(__hadd2(*(const __half2*)&av.y, *(const __half2*)&ov.y), hz);
            *(__half2*)&r.z = __hmax2(__hadd2(*(const __half2*)&av.z, *(const __half2*)&ov.z), hz);
            *(__half2*)&r.w = __hmax2(__hadd2(*(const __half2*)&av.w, *(const __half2*)&ov.w), hz);
            *(uint4*)&As[m][c8 * 8] = r;
        }
        // fill Bs: 80 rows x 6 chunks = 480, 2 per thread (predicated), pure copy
#pragma unroll
        for (int s = 0; s < 2; s++) {
            int id = t + s * 256;
            if (id < 480) {
                int n = id / 6, c8 = id % 6;
                *(uint4*)&Bs[n][c8 * 8] =
                    *(const uint4*)(g_Wh + (size_t)(n0 + n) * D_P1 + k0 + c8 * 8);
            }
        }
        __syncthreads();
#pragma unroll
        for (int kt = 0; kt < 3; kt++) {
            const int kk = kt * 16;   // half index within chunk
            unsigned a[2][4], b[5][2];
#pragma unroll
            for (int mt = 0; mt < 2; mt++)
                ldsm_x4(a[mt][0], a[mt][1], a[mt][2], a[mt][3],
                        offA + (uint32_t)((((wm * 32 + mt * 16) * PG_KH) + kk) * 2));
            ldsm_x4(b[0][0], b[0][1], b[1][0], b[1][1],
                    offB4 + (uint32_t)((((wn * 40 + 0) * PG_KH) + kk) * 2));
            ldsm_x4(b[2][0], b[2][1], b[3][0], b[3][1],
                    offB4 + (uint32_t)((((wn * 40 + 16) * PG_KH) + kk) * 2));
            ldsm_x2(b[4][0], b[4][1],
                    offB2 + (uint32_t)((((wn * 40 + 32) * PG_KH) + kk) * 2));
#pragma unroll
            for (int mt = 0; mt < 2; mt++)
#pragma unroll
                for (int nt = 0; nt < 5; nt++)
                    mma_f16(acc[mt][nt], a[mt], b[nt]);
        }
    }
    // epilogue: + bias, store to g_qh (half2)
#pragma unroll
    for (int mt = 0; mt < 2; mt++) {
        int row0 = m0 + wm * 32 + mt * 16 + gid;
        int row1 = row0 + 8;
#pragma unroll
        for (int nt = 0; nt < 5; nt++) {
            int col = n0 + wn * 40 + nt * 8 + 2 * tig;
            float b0 = bias[col], b1 = bias[col + 1];
            if (row0 < NPAIR)
                *(__half2*)(g_qh + (size_t)row0 * EMB + col) =
                    __floats2half2_rn(acc[mt][nt][0] + b0, acc[mt][nt][1] + b1);
            if (row1 < NPAIR)
                *(__half2*)(g_qh + (size_t)row1 * EMB + col) =
                    __floats2half2_rn(acc[mt][nt][2] + b0, acc[mt][nt][3] + b1);
        }
    }
}

// ---------------- per-row mean / rstd of q (single pass, half source) ----------------
__global__ void k_rowstats() {
    int w = threadIdx.x >> 5, lane = threadIdx.x & 31;
    int row = blockIdx.x * 8 + w;
    if (row >= NPAIR) return;
    const __half2* x = (const __half2*)(g_qh + (size_t)row * EMB);
    float s = 0.f, s2 = 0.f;
    for (int i = lane; i < EMB / 2; i += 32) {
        float2 v = __half22float2(x[i]);
        s += v.x + v.y;
        s2 = fmaf(v.x, v.x, fmaf(v.y, v.y, s2));
    }
#pragma unroll
    for (int o = 16; o; o >>= 1) {
        s += __shfl_xor_sync(0xffffffffu, s, o);
        s2 += __shfl_xor_sync(0xffffffffu, s2, o);
    }
    if (lane == 0) {
        float m = s * (1.f / EMB);
        float var = fmaxf(s2 * (1.f / EMB) - m * m, 0.f);
        g_mean[row] = m;
        g_rstd[row] = rsqrtf(var + LN_EPS);
    }
}

// ---------------- image LN + fold gp/bpn ----------------
__device__ __forceinline__ float blk_sum(float v) {
    __shared__ float sh[8];
    int lane = threadIdx.x & 31, w = threadIdx.x >> 5;
#pragma unroll
    for (int o = 16; o; o >>= 1) v += __shfl_xor_sync(0xffffffffu, v, o);
    if (lane == 0) sh[w] = v;
    __syncthreads();
    v = (threadIdx.x < 8) ? sh[threadIdx.x] : 0.f;
    if (w == 0) {
#pragma unroll
        for (int o = 4; o; o >>= 1) v += __shfl_xor_sync(0xffffffffu, v, o);
        if (lane == 0) sh[0] = v;
    }
    __syncthreads();
    float r = sh[0];
    __syncthreads();
    return r;
}

__global__ void __launch_bounds__(256) k_img_ln(const float* __restrict__ gi,
                                                const float* __restrict__ bin_,
                                                const float* __restrict__ gp,
                                                const float* __restrict__ bpn)
{
    int row = blockIdx.x;
    const float* x = g_i3 + (size_t)row * EMB;
    int t = threadIdx.x;
    float x0 = x[t], x1 = x[t + 256], x2 = x[t + 512];
    float x3 = (t < 32) ? x[t + 768] : 0.f;
    float s = blk_sum(x0 + x1 + x2 + x3);
    float m = s * (1.f / EMB);
    float d0 = x0 - m, d1 = x1 - m, d2 = x2 - m;
    float d3 = (t < 32) ? (x3 - m) : 0.f;
    float var = blk_sum(d0 * d0 + d1 * d1 + d2 * d2 + d3 * d3);
    float rstd = rsqrtf(var * (1.f / EMB) + LN_EPS);
    float sb = 0.f, cbv = 0.f;
#pragma unroll
    for (int rep = 0; rep < 4; rep++) {
        int e = t + rep * 256;
        if (rep < 3 || t < 32) {
            float iv = (x[e] - m) * rstd * gi[e] + bin_[e];
            float igv = iv * gp[e];
            g_ig[(size_t)row * EMB + e] = igv;
            sb += igv;
            cbv += iv * bpn[e];
        }
    }
    sb = blk_sum(sb);
    cbv = blk_sum(cbv);
    if (t == 0) { g_Sb[row] = sb; g_cb[row] = cbv; }
}

// ---------------- final fused GEMM + LN epilogue (fp16 + ldmatrix, half q) -------------
// out[b,k] = (ig[b].q[k] - mean_k*Sb[b])*rstd_k + cb[b]
// BM=128, BN=128, BK=32 halves. 8 warps: warp grid 2(m) x 4(n), warp tile 64x32.
#define KF_KH 40   // 32 + 8 pad (halves)
__global__ void __launch_bounds__(256, 2) k_final(float* __restrict__ out) {
    __shared__ __align__(16) __half As[128][KF_KH];
    __shared__ __align__(16) __half Bs[128][KF_KH];
    const int t = threadIdx.x;
    const int m0 = blockIdx.y * 128;
    const int n0 = blockIdx.x * 128;
    const int wid = t >> 5, lane = t & 31;
    const int wm = wid & 1;          // rows wm*64
    const int wn = wid >> 1;         // cols wn*32
    const int gid = lane >> 2, tig = lane & 3;

    const uint32_t smA = (uint32_t)__cvta_generic_to_shared(&As[0][0]);
    const uint32_t smB = (uint32_t)__cvta_generic_to_shared(&Bs[0][0]);
    const uint32_t offA = smA + (uint32_t)((((lane & 7) + ((lane >> 3) & 1) * 8) * KF_KH) * 2
                                           + ((lane >> 4) & 1) * 16);
    const uint32_t offB4 = smB + (uint32_t)((((lane & 7) + (lane >> 4) * 8) * KF_KH) * 2
                                            + ((lane >> 3) & 1) * 16);

    float acc[4][4][4];
#pragma unroll
    for (int mt = 0; mt < 4; mt++)
#pragma unroll
        for (int nt = 0; nt < 4; nt++)
#pragma unroll
            for (int r = 0; r < 4; r++) acc[mt][nt][r] = 0.f;

    for (int k0 = 0; k0 < EMB; k0 += 32) {
        __syncthreads();
        // As: fp32 ig + cvt; Bs: direct half copy from g_qh. 1024 quad4s each, 4/thread.
#pragma unroll
        for (int s = 0; s < 4; s++) {
            int id = t + s * 256;
            int m = id >> 3, c4 = id & 7;
            const float4 a4 = *(const float4*)(g_ig + (size_t)(m0 + m) * EMB + k0 + c4 * 4);
            *(__half2*)&As[m][c4 * 4]     = __floats2half2_rn(a4.x, a4.y);
            *(__half2*)&As[m][c4 * 4 + 2] = __floats2half2_rn(a4.z, a4.w);
            int nrow = n0 + m;
            if (nrow > NPAIR - 1) nrow = NPAIR - 1;
            *(uint2*)&Bs[m][c4 * 4] =
                *(const uint2*)(g_qh + (size_t)nrow * EMB + k0 + c4 * 4);
        }
        __syncthreads();
#pragma unroll
        for (int kt = 0; kt < 2; kt++) {
            const int kk = kt * 16;
            unsigned a[4][4], b[4][2];
#pragma unroll
            for (int mt = 0; mt < 4; mt++)
                ldsm_x4(a[mt][0], a[mt][1], a[mt][2], a[mt][3],
                        offA + (uint32_t)((((wm * 64 + mt * 16) * KF_KH) + kk) * 2));
            ldsm_x4(b[0][0], b[0][1], b[1][0], b[1][1],
                    offB4 + (uint32_t)((((wn * 32 + 0) * KF_KH) + kk) * 2));
            ldsm_x4(b[2][0], b[2][1], b[3][0], b[3][1],
                    offB4 + (uint32_t)((((wn * 32 + 16) * KF_KH) + kk) * 2));
#pragma unroll
            for (int mt = 0; mt < 4; mt++)
#pragma unroll
                for (int nt = 0; nt < 4; nt++)
                    mma_f16(acc[mt][nt], a[mt], b[nt]);
        }
    }

    // LN epilogue on fragments
#pragma unroll
    for (int mt = 0; mt < 4; mt++) {
        int row0 = m0 + wm * 64 + mt * 16 + gid;
        int row1 = row0 + 8;
        float sb0 = g_Sb[row0], cb0 = g_cb[row0];
        float sb1 = g_Sb[row1], cb1 = g_cb[row1];
#pragma unroll
        for (int nt = 0; nt < 4; nt++) {
            int col = n0 + wn * 32 + nt * 8 + 2 * tig;
            int c0 = col < NPAIR ? col : NPAIR - 1;
            int c1 = col + 1 < NPAIR ? col + 1 : NPAIR - 1;
            float mn0 = g_mean[c0], rs0 = g_rstd[c0];
            float mn1 = g_mean[c1], rs1 = g_rstd[c1];
            if (col + 1 < NPAIR) {
                float2 v0 = make_float2((acc[mt][nt][0] - mn0 * sb0) * rs0 + cb0,
                                        (acc[mt][nt][1] - mn1 * sb0) * rs1 + cb0);
                *(float2*)(out + (size_t)row0 * NPAIR + col) = v0;
                float2 v1 = make_float2((acc[mt][nt][2] - mn0 * sb1) * rs0 + cb1,
                                        (acc[mt][nt][3] - mn1 * sb1) * rs1 + cb1);
                *(float2*)(out + (size_t)row1 * NPAIR + col) = v1;
            } else if (col < NPAIR) {
                out[(size_t)row0 * NPAIR + col] = (acc[mt][nt][0] - mn0 * sb0) * rs0 + cb0;
                out[(size_t)row1 * NPAIR + col] = (acc[mt][nt][2] - mn0 * sb1) * rs0 + cb1;
            }
        }
    }
}

// ---------------- launch ----------------
extern "C" void kernel_launch(void* const* d_in, const int* in_sizes, int n_in,
                              void* d_out, int out_size)
{
    const float* img  = (const float*)d_in[0];
    const float* nodes = (const float*)d_in[1];
    const int*   esrc = (const int*)d_in[2];
    const int*   edst = (const int*)d_in[3];
    const float* W1l  = (const float*)d_in[4];
    const float* b1   = (const float*)d_in[5];
    const float* W1r  = (const float*)d_in[6];
    const float* W2l  = (const float*)d_in[7];
    const float* b2   = (const float*)d_in[8];
    const float* W2r  = (const float*)d_in[9];
    const float* Wp1  = (const float*)d_in[10];
    const float* bp1  = (const float*)d_in[11];
    const float* Wp2  = (const float*)d_in[12];
    const float* bp2  = (const float*)d_in[13];
    const float* gp   = (const float*)d_in[14];
    const float* bpn  = (const float*)d_in[15];
    const float* Wi1  = (const float*)d_in[16];
    const float* bi1  = (const float*)d_in[17];
    const float* Wi2  = (const float*)d_in[18];
    const float* bi2  = (const float*)d_in[19];
    const float* Wi3  = (const float*)d_in[20];
    const float* bi3  = (const float*)d_in[21];
    const float* gi   = (const float*)d_in[22];
    const float* bin_ = (const float*)d_in[23];
    float* out = (float*)d_out;

    float *aggM, *h, *outn, *Abuf, *Obuf, *i1, *i2, *i3;
    __half *Ah, *Oh, *Wh;
    cudaGetSymbolAddress((void**)&aggM, g_aggM);
    cudaGetSymbolAddress((void**)&h,    g_h);
    cudaGetSymbolAddress((void**)&outn, g_outn);
    cudaGetSymbolAddress((void**)&Abuf, g_A);
    cudaGetSymbolAddress((void**)&Obuf, g_O);
    cudaGetSymbolAddress((void**)&Ah,   g_Ah);
    cudaGetSymbolAddress((void**)&Oh,   g_Oh);
    cudaGetSymbolAddress((void**)&Wh,   g_Wh);
    cudaGetSymbolAddress((void**)&i1,   g_img1);
    cudaGetSymbolAddress((void**)&i2,   g_img2);
    cudaGetSymbolAddress((void**)&i3,   g_i3);

    // CSR
    k_zero_cnt<<<3, 256>>>();
    k_count<<<(NEDGE + 255) / 256, 256>>>(edst);
    k_scan<<<1, 1024>>>();
    k_fill<<<(NEDGE + 255) / 256, 256>>>(esrc, edst);

    // Wp2 -> half (independent of graph pipeline)
    k_cvt_half<<<(EMB * D_P1 / 4 + 255) / 256, 256>>>(Wp2, Wh, EMB * D_P1 / 4);

    // SAGE layer 1: h = relu(mean(nodes) @ W1l^T + b1 + nodes @ W1r^T)
    k_gather<<<dim3(NNODE, D_IN / 256), 256>>>(nodes, aggM, D_IN);
    gemm64<true, true><<<dim3(D_HID / 64, (NNODE + 63) / 64), 256>>>(
        aggM, D_IN, W1l, D_IN, D_IN,
        nodes, D_IN, W1r, D_IN, D_IN,
        b1, h, D_HID, NNODE, D_HID);

    // SAGE layer 2: outn = mean(h) @ W2l^T + b2 + h @ W2r^T
    k_gather<<<dim3(NNODE, D_HID / 256), 256>>>(h, aggM, D_HID);
    gemm64<false, true><<<dim3(D_NODE / 64, (NNODE + 63) / 64), 256>>>(
        aggM, D_HID, W2l, D_HID, D_HID,
        h, D_HID, W2r, D_HID, D_HID,
        b2, outn, D_NODE, NNODE, D_NODE);

    // pair pre-factors: A = attr @ Wp1[:, :512]^T + bp1 ; O = obj @ Wp1[:, 512:]^T
    gemm64<false, false><<<dim3((D_P1 + 63) / 64, (NATTR + 63) / 64), 256>>>(
        outn, D_NODE, Wp1, 2 * D_NODE, D_NODE,
        nullptr, 0, nullptr, 0, 0,
        bp1, Abuf, D_P1, NATTR, D_P1);
    gemm64<false, false><<<dim3((D_P1 + 63) / 64, (NOBJ + 63) / 64), 256>>>(
        outn + NATTR * D_NODE, D_NODE, Wp1 + D_NODE, 2 * D_NODE, D_NODE,
        nullptr, 0, nullptr, 0, 0,
        nullptr, Obuf, D_P1, NOBJ, D_P1);
    k_cvt_half<<<(NATTR * D_P1 / 4 + 255) / 256, 256>>>(Abuf, Ah, NATTR * D_P1 / 4);
    k_cvt_half<<<(NOBJ * D_P1 / 4 + 255) / 256, 256>>>(Obuf, Oh, NOBJ * D_P1 / 4);

    // image MLP
    gemm64<true, false><<<dim3(768 / 64, BIMG / 64), 256>>>(
        img, FEAT, Wi1, FEAT, FEAT,
        nullptr, 0, nullptr, 0, 0,
        bi1, i1, 768, BIMG, 768);
    gemm64<true, false><<<dim3((1000 + 63) / 64, BIMG / 64), 256>>>(
        i1, 768, Wi2, 768, 768,
        nullptr, 0, nullptr, 0, 0,
        bi2, i2, 1000, BIMG, 1000);
    gemm64<false, false><<<dim3((EMB + 63) / 64, BIMG / 64), 256>>>(
        i2, 1000, Wi3, 1000, 1000,
        nullptr, 0, nullptr, 0, 0,
        bi3, i3, EMB, BIMG, EMB);
    k_img_ln<<<BIMG, 256>>>(gi, bin_, gp, bpn);

    // big pair GEMM -> g_qh (fp16 tensor cores + ldmatrix, half operands)
    pair_gemm<<<dim3(EMB / 80, (NPAIR + 127) / 128), 256>>>(bp2);

    // LN row stats (single pass over half q)
    k_rowstats<<<NPAIR / 8, 256>>>();

    // final fused GEMM + LN epilogue (fp16 + ldmatrix)
    k_final<<<dim3((NPAIR + 127) / 128, BIMG / 128), 256>>>(out);
}

// round 16
// speedup vs baseline: 1.5512x; 1.5512x over previous
#include <cuda_runtime.h>
#include <cuda_fp16.h>
#include <cuda_bf16.h>
#include <cstdint>
#include <cstddef>

// ---------------- problem constants ----------------
#define NNODE   650
#define NATTR   250
#define NOBJ    400
#define NEDGE   100000
#define NPAIR   100000      // 250*400
#define D_IN    512
#define D_HID   4096
#define D_NODE  512
#define D_P1    1200
#define EMB     800
#define FEAT    2048
#define BIMG    256
#define LN_EPS  1e-5f

// ---------------- device scratch (static; no runtime alloc) ----------------
__device__ float g_aggM[NNODE * D_HID];
__device__ float g_h[NNODE * D_HID];
__device__ float g_outn[NNODE * D_NODE];
__device__ float g_A[NATTR * D_P1];
__device__ float g_O[NOBJ * D_P1];
__device__ __half g_Ah[NATTR * D_P1];
__device__ __half g_Oh[NOBJ * D_P1];
__device__ __half g_Wh[EMB * D_P1];
__device__ float g_img1[BIMG * 768];
__device__ float g_img2[BIMG * 1000];
__device__ float g_i3[BIMG * EMB];
__device__ float g_ig[BIMG * EMB];
__device__ float g_Sb[BIMG];
__device__ float g_cb[BIMG];
__device__ __half g_qh[NPAIR * EMB];          // 160 MB pair pre-LN activations (half)
__device__ float g_mean[NPAIR];
__device__ float g_rstd[NPAIR];
__device__ float g_deginv[NNODE];
__device__ int   g_cnt[NNODE];
__device__ int   g_offs[NNODE + 1];
__device__ int   g_cursor[NNODE];
__device__ int   g_csr[NEDGE];

// ---------------- fp16 mma / ldmatrix helpers ----------------
// D(16x8,f32) += A(16x16,f16,row) * B(16x8,f16,col)
__device__ __forceinline__ void mma_f16(float* c, const unsigned* a, const unsigned* b) {
    asm volatile(
        "mma.sync.aligned.m16n8k16.row.col.f32.f16.f16.f32 "
        "{%0,%1,%2,%3}, {%4,%5,%6,%7}, {%8,%9}, {%0,%1,%2,%3};"
        : "+f"(c[0]), "+f"(c[1]), "+f"(c[2]), "+f"(c[3])
        : "r"(a[0]), "r"(a[1]), "r"(a[2]), "r"(a[3]), "r"(b[0]), "r"(b[1]));
}

__device__ __forceinline__ void ldsm_x4(unsigned& r0, unsigned& r1, unsigned& r2, unsigned& r3,
                                        uint32_t addr) {
    asm volatile("ldmatrix.sync.aligned.m8n8.x4.shared.b16 {%0,%1,%2,%3}, [%4];"
                 : "=r"(r0), "=r"(r1), "=r"(r2), "=r"(r3) : "r"(addr));
}
__device__ __forceinline__ void ldsm_x2(unsigned& r0, unsigned& r1, uint32_t addr) {
    asm volatile("ldmatrix.sync.aligned.m8n8.x2.shared.b16 {%0,%1}, [%2];"
                 : "=r"(r0), "=r"(r1) : "r"(addr));
}

// ---------------- fp32 -> fp16 convert ----------------
__global__ void k_cvt_half(const float* __restrict__ src, __half* __restrict__ dst, int n4) {
    int i = blockIdx.x * blockDim.x + threadIdx.x;
    if (i < n4) {
        float4 v = ((const float4*)src)[i];
        ((__half2*)dst)[2 * i]     = __floats2half2_rn(v.x, v.y);
        ((__half2*)dst)[2 * i + 1] = __floats2half2_rn(v.z, v.w);
    }
}

// ---------------- CSR build ----------------
__global__ void k_zero_cnt() {
    int t = blockIdx.x * blockDim.x + threadIdx.x;
    if (t < NNODE) g_cnt[t] = 0;
}

__global__ void k_count(const int* __restrict__ dst) {
    int e = blockIdx.x * blockDim.x + threadIdx.x;
    if (e < NEDGE) atomicAdd(&g_cnt[dst[e]], 1);
}

__global__ void k_scan() {
    __shared__ int s[NNODE + 1];
    int t = threadIdx.x;                 // 1024 threads
    if (t < NNODE) s[t + 1] = g_cnt[t];
    if (t == 0) s[0] = 0;
    __syncthreads();
    for (int d = 1; d < NNODE + 1; d <<= 1) {
        int v = 0;
        if (t < NNODE + 1 && t >= d) v = s[t - d];
        __syncthreads();
        if (t < NNODE + 1 && t >= d) s[t] += v;
        __syncthreads();
    }
    if (t < NNODE + 1) g_offs[t] = s[t];
    if (t < NNODE) {
        g_cursor[t] = s[t];
        g_deginv[t] = 1.0f / fmaxf((float)g_cnt[t], 1.0f);
    }
}

__global__ void k_fill(const int* __restrict__ src, const int* __restrict__ dst) {
    int e = blockIdx.x * blockDim.x + threadIdx.x;
    if (e < NEDGE) {
        int p = atomicAdd(&g_cursor[dst[e]], 1);
        g_csr[p] = src[e];
    }
}

// ---------------- segment mean via CSR gather ----------------
__global__ void k_gather(const float* __restrict__ X, float* __restrict__ out, int D) {
    int n = blockIdx.x;
    int f = blockIdx.y * 256 + threadIdx.x;
    int beg = g_offs[n], end = g_offs[n + 1];
    float inv = g_deginv[n];
    float a0 = 0.f, a1 = 0.f, a2 = 0.f, a3 = 0.f;
    int e = beg;
    for (; e + 4 <= end; e += 4) {
        int s0 = g_csr[e], s1 = g_csr[e + 1], s2 = g_csr[e + 2], s3 = g_csr[e + 3];
        a0 += X[(size_t)s0 * D + f];
        a1 += X[(size_t)s1 * D + f];
        a2 += X[(size_t)s2 * D + f];
        a3 += X[(size_t)s3 * D + f];
    }
    for (; e < end; e++) a0 += X[(size_t)g_csr[e] * D + f];
    out[(size_t)n * D + f] = (a0 + a1 + a2 + a3) * inv;
}

// ---------------- generic small GEMM: C = act(A@B^T (+ A2@B2^T) + bias) ----------------
template<bool RELU, bool DUAL>
__global__ void __launch_bounds__(256) gemm64(
    const float* __restrict__ A, int lda, const float* __restrict__ B, int ldb, int K,
    const float* __restrict__ A2, int lda2, const float* __restrict__ B2, int ldb2, int K2,
    const float* __restrict__ bias, float* __restrict__ C, int ldc, int M, int N)
{
    __shared__ float As[8][65];
    __shared__ float Bs[8][65];
    const int t = threadIdx.x;
    const int m0 = blockIdx.y * 64, n0 = blockIdx.x * 64;
    const int tx = t & 15, ty = t >> 4;
    float acc[4][4];
#pragma unroll
    for (int i = 0; i < 4; i++)
#pragma unroll
        for (int j = 0; j < 4; j++) acc[i][j] = 0.f;

    const int npass = DUAL ? 2 : 1;
    for (int pass = 0; pass < npass; pass++) {
        const float* Ap = pass ? A2 : A;
        const float* Bp = pass ? B2 : B;
        const int ldap = pass ? lda2 : lda;
        const int ldbp = pass ? ldb2 : ldb;
        const int Kp = pass ? K2 : K;
        for (int k0 = 0; k0 < Kp; k0 += 8) {
            __syncthreads();
#pragma unroll
            for (int s = 0; s < 2; s++) {
                int id = t + s * 256;
                int m = id >> 3, k = id & 7;
                As[k][m] = (m0 + m < M) ? Ap[(size_t)(m0 + m) * ldap + k0 + k] : 0.f;
                Bs[k][m] = (n0 + m < N) ? Bp[(size_t)(n0 + m) * ldbp + k0 + k] : 0.f;
            }
            __syncthreads();
#pragma unroll
            for (int kk = 0; kk < 8; kk++) {
                float a[4], b[4];
#pragma unroll
                for (int i = 0; i < 4; i++) a[i] = As[kk][ty * 4 + i];
#pragma unroll
                for (int j = 0; j < 4; j++) b[j] = Bs[kk][tx * 4 + j];
#pragma unroll
                for (int i = 0; i < 4; i++)
#pragma unroll
                    for (int j = 0; j < 4; j++)
                        acc[i][j] = fmaf(a[i], b[j], acc[i][j]);
            }
        }
    }
#pragma unroll
    for (int i = 0; i < 4; i++) {
        int m = m0 + ty * 4 + i;
        if (m >= M) continue;
#pragma unroll
        for (int j = 0; j < 4; j++) {
            int n = n0 + tx * 4 + j;
            if (n >= N) continue;
            float v = acc[i][j] + (bias ? bias[n] : 0.f);
            if (RELU) v = fmaxf(v, 0.f);
            C[(size_t)m * ldc + n] = v;
        }
    }
}

// ---------------- big pair GEMM (fp16 mma + ldmatrix + reg-staged pipeline) ------------
// q[p,n] = relu(A[i(p)]+O[j(p)]) @ Wp2^T + bp2, all operands half.
// BM=128, BN=80, BK=48 halves, 25 chunks. 8 warps: 4(m) x 2(n), warp tile 32x40.
// Per chunk: store staged regs -> smem, issue next chunk's LDGs, then mma —
// global-load latency overlaps the mma stream.
#define PG_KH 56   // 48 + 8 pad (halves)
__global__ void __launch_bounds__(256, 2) pair_gemm(const float* __restrict__ bias)
{
    __shared__ __align__(16) __half As[128][PG_KH];
    __shared__ __align__(16) __half Bs[80][PG_KH];
    __shared__ int arow[128];
    __shared__ int orow[128];
    const int t = threadIdx.x;
    const int m0 = blockIdx.y * 128;
    const int n0 = blockIdx.x * 80;
    if (t < 128) {
        int p = m0 + t;
        if (p > NPAIR - 1) p = NPAIR - 1;
        int ii = p / NOBJ;
        arow[t] = ii * D_P1;
        orow[t] = (p - ii * NOBJ) * D_P1;
    }
    const int wid = t >> 5, lane = t & 31;
    const int wm = wid & 3;          // rows wm*32
    const int wn = wid >> 2;         // cols wn*40
    const int gid = lane >> 2, tig = lane & 3;

    // per-thread fill coordinates (constant across chunks)
    int mA[3], cA[3];
#pragma unroll
    for (int s = 0; s < 3; s++) { int id = t + s * 256; mA[s] = id / 6; cA[s] = (id % 6) * 8; }
    int nB[2], cB[2];
    bool vB[2];
#pragma unroll
    for (int s = 0; s < 2; s++) {
        int id = t + s * 256;
        vB[s] = (id < 480);
        int idc = vB[s] ? id : 0;
        nB[s] = idc / 6; cB[s] = (idc % 6) * 8;
    }

    const uint32_t smA = (uint32_t)__cvta_generic_to_shared(&As[0][0]);
    const uint32_t smB = (uint32_t)__cvta_generic_to_shared(&Bs[0][0]);
    const uint32_t offA = smA + (uint32_t)((((lane & 7) + ((lane >> 3) & 1) * 8) * PG_KH) * 2
                                           + ((lane >> 4) & 1) * 16);
    const uint32_t offB4 = smB + (uint32_t)((((lane & 7) + (lane >> 4) * 8) * PG_KH) * 2
                                            + ((lane >> 3) & 1) * 16);
    const uint32_t offB2 = smB + (uint32_t)(((lane & 7) * PG_KH) * 2
                                            + ((lane >> 3) & 1) * 16);

    float acc[2][5][4];
#pragma unroll
    for (int mt = 0; mt < 2; mt++)
#pragma unroll
        for (int nt = 0; nt < 5; nt++)
#pragma unroll
            for (int r = 0; r < 4; r++) acc[mt][nt][r] = 0.f;

    const __half2 hz = __float2half2_rn(0.f);

    __syncthreads();   // arow/orow visible before first staged load

    // prefetch registers for the pipeline
    uint4 pa[3], po[3], pb[2];
#pragma unroll
    for (int s = 0; s < 3; s++) {
        pa[s] = *(const uint4*)(g_Ah + arow[mA[s]] + cA[s]);
        po[s] = *(const uint4*)(g_Oh + orow[mA[s]] + cA[s]);
    }
#pragma unroll
    for (int s = 0; s < 2; s++)
        if (vB[s]) pb[s] = *(const uint4*)(g_Wh + (size_t)(n0 + nB[s]) * D_P1 + cB[s]);

    for (int c = 0; c < 25; c++) {
        __syncthreads();   // previous chunk's mma done reading smem
        // store staged regs -> smem (relu(A+O) in half2)
#pragma unroll
        for (int s = 0; s < 3; s++) {
            uint4 r;
            *(__half2*)&r.x = __hmax2(__hadd2(*(const __half2*)&pa[s].x, *(const __half2*)&po[s].x), hz);
            *(__half2*)&r.y = __hmax2(__hadd2(*(const __half2*)&pa[s].y, *(const __half2*)&po[s].y), hz);
            *(__half2*)&r.z = __hmax2(__hadd2(*(const __half2*)&pa[s].z, *(const __half2*)&po[s].z), hz);
            *(__half2*)&r.w = __hmax2(__hadd2(*(const __half2*)&pa[s].w, *(const __half2*)&po[s].w), hz);
            *(uint4*)&As[mA[s]][cA[s]] = r;
        }
#pragma unroll
        for (int s = 0; s < 2; s++)
            if (vB[s]) *(uint4*)&Bs[nB[s]][cB[s]] = pb[s];
        __syncthreads();
        // issue next chunk's loads — latency hidden by the mma below
        if (c + 1 < 25) {
            const int kn = (c + 1) * 48;
#pragma unroll
            for (int s = 0; s < 3; s++) {
                pa[s] = *(const uint4*)(g_Ah + arow[mA[s]] + kn + cA[s]);
                po[s] = *(const uint4*)(g_Oh + orow[mA[s]] + kn + cA[s]);
            }
#pragma unroll
            for (int s = 0; s < 2; s++)
                if (vB[s]) pb[s] = *(const uint4*)(g_Wh + (size_t)(n0 + nB[s]) * D_P1 + kn + cB[s]);
        }
#pragma unroll
        for (int kt = 0; kt < 3; kt++) {
            const int kk = kt * 16;   // half index within chunk
            unsigned a[2][4], b[5][2];
#pragma unroll
            for (int mt = 0; mt < 2; mt++)
                ldsm_x4(a[mt][0], a[mt][1], a[mt][2], a[mt][3],
                        offA + (uint32_t)((((wm * 32 + mt * 16) * PG_KH) + kk) * 2));
            ldsm_x4(b[0][0], b[0][1], b[1][0], b[1][1],
                    offB4 + (uint32_t)((((wn * 40 + 0) * PG_KH) + kk) * 2));
            ldsm_x4(b[2][0], b[2][1], b[3][0], b[3][1],
                    offB4 + (uint32_t)((((wn * 40 + 16) * PG_KH) + kk) * 2));
            ldsm_x2(b[4][0], b[4][1],
                    offB2 + (uint32_t)((((wn * 40 + 32) * PG_KH) + kk) * 2));
#pragma unroll
            for (int mt = 0; mt < 2; mt++)
#pragma unroll
                for (int nt = 0; nt < 5; nt++)
                    mma_f16(acc[mt][nt], a[mt], b[nt]);
        }
    }
    // epilogue: + bias, store to g_qh (half2)
#pragma unroll
    for (int mt = 0; mt < 2; mt++) {
        int row0 = m0 + wm * 32 + mt * 16 + gid;
        int row1 = row0 + 8;
#pragma unroll
        for (int nt = 0; nt < 5; nt++) {
            int col = n0 + wn * 40 + nt * 8 + 2 * tig;
            float b0 = bias[col], b1 = bias[col + 1];
            if (row0 < NPAIR)
                *(__half2*)(g_qh + (size_t)row0 * EMB + col) =
                    __floats2half2_rn(acc[mt][nt][0] + b0, acc[mt][nt][1] + b1);
            if (row1 < NPAIR)
                *(__half2*)(g_qh + (size_t)row1 * EMB + col) =
                    __floats2half2_rn(acc[mt][nt][2] + b0, acc[mt][nt][3] + b1);
        }
    }
}

// ---------------- per-row mean / rstd of q (single pass, half source) ----------------
__global__ void k_rowstats() {
    int w = threadIdx.x >> 5, lane = threadIdx.x & 31;
    int row = blockIdx.x * 8 + w;
    if (row >= NPAIR) return;
    const __half2* x = (const __half2*)(g_qh + (size_t)row * EMB);
    float s = 0.f, s2 = 0.f;
    for (int i = lane; i < EMB / 2; i += 32) {
        float2 v = __half22float2(x[i]);
        s += v.x + v.y;
        s2 = fmaf(v.x, v.x, fmaf(v.y, v.y, s2));
    }
#pragma unroll
    for (int o = 16; o; o >>= 1) {
        s += __shfl_xor_sync(0xffffffffu, s, o);
        s2 += __shfl_xor_sync(0xffffffffu, s2, o);
    }
    if (lane == 0) {
        float m = s * (1.f / EMB);
        float var = fmaxf(s2 * (1.f / EMB) - m * m, 0.f);
        g_mean[row] = m;
        g_rstd[row] = rsqrtf(var + LN_EPS);
    }
}

// ---------------- image LN + fold gp/bpn ----------------
__device__ __forceinline__ float blk_sum(float v) {
    __shared__ float sh[8];
    int lane = threadIdx.x & 31, w = threadIdx.x >> 5;
#pragma unroll
    for (int o = 16; o; o >>= 1) v += __shfl_xor_sync(0xffffffffu, v, o);
    if (lane == 0) sh[w] = v;
    __syncthreads();
    v = (threadIdx.x < 8) ? sh[threadIdx.x] : 0.f;
    if (w == 0) {
#pragma unroll
        for (int o = 4; o; o >>= 1) v += __shfl_xor_sync(0xffffffffu, v, o);
        if (lane == 0) sh[0] = v;
    }
    __syncthreads();
    float r = sh[0];
    __syncthreads();
    return r;
}

__global__ void __launch_bounds__(256) k_img_ln(const float* __restrict__ gi,
                                                const float* __restrict__ bin_,
                                                const float* __restrict__ gp,
                                                const float* __restrict__ bpn)
{
    int row = blockIdx.x;
    const float* x = g_i3 + (size_t)row * EMB;
    int t = threadIdx.x;
    float x0 = x[t], x1 = x[t + 256], x2 = x[t + 512];
    float x3 = (t < 32) ? x[t + 768] : 0.f;
    float s = blk_sum(x0 + x1 + x2 + x3);
    float m = s * (1.f / EMB);
    float d0 = x0 - m, d1 = x1 - m, d2 = x2 - m;
    float d3 = (t < 32) ? (x3 - m) : 0.f;
    float var = blk_sum(d0 * d0 + d1 * d1 + d2 * d2 + d3 * d3);
    float rstd = rsqrtf(var * (1.f / EMB) + LN_EPS);
    float sb = 0.f, cbv = 0.f;
#pragma unroll
    for (int rep = 0; rep < 4; rep++) {
        int e = t + rep * 256;
        if (rep < 3 || t < 32) {
            float iv = (x[e] - m) * rstd * gi[e] + bin_[e];
            float igv = iv * gp[e];
            g_ig[(size_t)row * EMB + e] = igv;
            sb += igv;
            cbv += iv * bpn[e];
        }
    }
    sb = blk_sum(sb);
    cbv = blk_sum(cbv);
    if (t == 0) { g_Sb[row] = sb; g_cb[row] = cbv; }
}

// ---------------- final fused GEMM + LN epilogue (fp16 + ldmatrix, half q) -------------
// out[b,k] = (ig[b].q[k] - mean_k*Sb[b])*rstd_k + cb[b]
// BM=128, BN=128, BK=32 halves. 8 warps: warp grid 2(m) x 4(n), warp tile 64x32.
#define KF_KH 40   // 32 + 8 pad (halves)
__global__ void __launch_bounds__(256, 2) k_final(float* __restrict__ out) {
    __shared__ __align__(16) __half As[128][KF_KH];
    __shared__ __align__(16) __half Bs[128][KF_KH];
    const int t = threadIdx.x;
    const int m0 = blockIdx.y * 128;
    const int n0 = blockIdx.x * 128;
    const int wid = t >> 5, lane = t & 31;
    const int wm = wid & 1;          // rows wm*64
    const int wn = wid >> 1;         // cols wn*32
    const int gid = lane >> 2, tig = lane & 3;

    const uint32_t smA = (uint32_t)__cvta_generic_to_shared(&As[0][0]);
    const uint32_t smB = (uint32_t)__cvta_generic_to_shared(&Bs[0][0]);
    const uint32_t offA = smA + (uint32_t)((((lane & 7) + ((lane >> 3) & 1) * 8) * KF_KH) * 2
                                           + ((lane >> 4) & 1) * 16);
    const uint32_t offB4 = smB + (uint32_t)((((lane & 7) + (lane >> 4) * 8) * KF_KH) * 2
                                            + ((lane >> 3) & 1) * 16);

    float acc[4][4][4];
#pragma unroll
    for (int mt = 0; mt < 4; mt++)
#pragma unroll
        for (int nt = 0; nt < 4; nt++)
#pragma unroll
            for (int r = 0; r < 4; r++) acc[mt][nt][r] = 0.f;

    for (int k0 = 0; k0 < EMB; k0 += 32) {
        __syncthreads();
        // As: fp32 ig + cvt; Bs: direct half copy from g_qh. 1024 quad4s each, 4/thread.
#pragma unroll
        for (int s = 0; s < 4; s++) {
            int id = t + s * 256;
            int m = id >> 3, c4 = id & 7;
            const float4 a4 = *(const float4*)(g_ig + (size_t)(m0 + m) * EMB + k0 + c4 * 4);
            *(__half2*)&As[m][c4 * 4]     = __floats2half2_rn(a4.x, a4.y);
            *(__half2*)&As[m][c4 * 4 + 2] = __floats2half2_rn(a4.z, a4.w);
            int nrow = n0 + m;
            if (nrow > NPAIR - 1) nrow = NPAIR - 1;
            *(uint2*)&Bs[m][c4 * 4] =
                *(const uint2*)(g_qh + (size_t)nrow * EMB + k0 + c4 * 4);
        }
        __syncthreads();
#pragma unroll
        for (int kt = 0; kt < 2; kt++) {
            const int kk = kt * 16;
            unsigned a[4][4], b[4][2];
#pragma unroll
            for (int mt = 0; mt < 4; mt++)
                ldsm_x4(a[mt][0], a[mt][1], a[mt][2], a[mt][3],
                        offA + (uint32_t)((((wm * 64 + mt * 16) * KF_KH) + kk) * 2));
            ldsm_x4(b[0][0], b[0][1], b[1][0], b[1][1],
                    offB4 + (uint32_t)((((wn * 32 + 0) * KF_KH) + kk) * 2));
            ldsm_x4(b[2][0], b[2][1], b[3][0], b[3][1],
                    offB4 + (uint32_t)((((wn * 32 + 16) * KF_KH) + kk) * 2));
#pragma unroll
            for (int mt = 0; mt < 4; mt++)
#pragma unroll
                for (int nt = 0; nt < 4; nt++)
                    mma_f16(acc[mt][nt], a[mt], b[nt]);
        }
    }

    // LN epilogue on fragments
#pragma unroll
    for (int mt = 0; mt < 4; mt++) {
        int row0 = m0 + wm * 64 + mt * 16 + gid;
        int row1 = row0 + 8;
        float sb0 = g_Sb[row0], cb0 = g_cb[row0];
        float sb1 = g_Sb[row1], cb1 = g_cb[row1];
#pragma unroll
        for (int nt = 0; nt < 4; nt++) {
            int col = n0 + wn * 32 + nt * 8 + 2 * tig;
            int c0 = col < NPAIR ? col : NPAIR - 1;
            int c1 = col + 1 < NPAIR ? col + 1 : NPAIR - 1;
            float mn0 = g_mean[c0], rs0 = g_rstd[c0];
            float mn1 = g_mean[c1], rs1 = g_rstd[c1];
            if (col + 1 < NPAIR) {
                float2 v0 = make_float2((acc[mt][nt][0] - mn0 * sb0) * rs0 + cb0,
                                        (acc[mt][nt][1] - mn1 * sb0) * rs1 + cb0);
                *(float2*)(out + (size_t)row0 * NPAIR + col) = v0;
                float2 v1 = make_float2((acc[mt][nt][2] - mn0 * sb1) * rs0 + cb1,
                                        (acc[mt][nt][3] - mn1 * sb1) * rs1 + cb1);
                *(float2*)(out + (size_t)row1 * NPAIR + col) = v1;
            } else if (col < NPAIR) {
                out[(size_t)row0 * NPAIR + col] = (acc[mt][nt][0] - mn0 * sb0) * rs0 + cb0;
                out[(size_t)row1 * NPAIR + col] = (acc[mt][nt][2] - mn0 * sb1) * rs0 + cb1;
            }
        }
    }
}

// ---------------- launch ----------------
extern "C" void kernel_launch(void* const* d_in, const int* in_sizes, int n_in,
                              void* d_out, int out_size)
{
    const float* img  = (const float*)d_in[0];
    const float* nodes = (const float*)d_in[1];
    const int*   esrc = (const int*)d_in[2];
    const int*   edst = (const int*)d_in[3];
    const float* W1l  = (const float*)d_in[4];
    const float* b1   = (const float*)d_in[5];
    const float* W1r  = (const float*)d_in[6];
    const float* W2l  = (const float*)d_in[7];
    const float* b2   = (const float*)d_in[8];
    const float* W2r  = (const float*)d_in[9];
    const float* Wp1  = (const float*)d_in[10];
    const float* bp1  = (const float*)d_in[11];
    const float* Wp2  = (const float*)d_in[12];
    const float* bp2  = (const float*)d_in[13];
    const float* gp   = (const float*)d_in[14];
    const float* bpn  = (const float*)d_in[15];
    const float* Wi1  = (const float*)d_in[16];
    const float* bi1  = (const float*)d_in[17];
    const float* Wi2  = (const float*)d_in[18];
    const float* bi2  = (const float*)d_in[19];
    const float* Wi3  = (const float*)d_in[20];
    const float* bi3  = (const float*)d_in[21];
    const float* gi   = (const float*)d_in[22];
    const float* bin_ = (const float*)d_in[23];
    float* out = (float*)d_out;

    float *aggM, *h, *outn, *Abuf, *Obuf, *i1, *i2, *i3;
    __half *Ah, *Oh, *Wh;
    cudaGetSymbolAddress((void**)&aggM, g_aggM);
    cudaGetSymbolAddress((void**)&h,    g_h);
    cudaGetSymbolAddress((void**)&outn, g_outn);
    cudaGetSymbolAddress((void**)&Abuf, g_A);
    cudaGetSymbolAddress((void**)&Obuf, g_O);
    cudaGetSymbolAddress((void**)&Ah,   g_Ah);
    cudaGetSymbolAddress((void**)&Oh,   g_Oh);
    cudaGetSymbolAddress((void**)&Wh,   g_Wh);
    cudaGetSymbolAddress((void**)&i1,   g_img1);
    cudaGetSymbolAddress((void**)&i2,   g_img2);
    cudaGetSymbolAddress((void**)&i3,   g_i3);

    // CSR
    k_zero_cnt<<<3, 256>>>();
    k_count<<<(NEDGE + 255) / 256, 256>>>(edst);
    k_scan<<<1, 1024>>>();
    k_fill<<<(NEDGE + 255) / 256, 256>>>(esrc, edst);

    // Wp2 -> half (independent of graph pipeline)
    k_cvt_half<<<(EMB * D_P1 / 4 + 255) / 256, 256>>>(Wp2, Wh, EMB * D_P1 / 4);

    // SAGE layer 1: h = relu(mean(nodes) @ W1l^T + b1 + nodes @ W1r^T)
    k_gather<<<dim3(NNODE, D_IN / 256), 256>>>(nodes, aggM, D_IN);
    gemm64<true, true><<<dim3(D_HID / 64, (NNODE + 63) / 64), 256>>>(
        aggM, D_IN, W1l, D_IN, D_IN,
        nodes, D_IN, W1r, D_IN, D_IN,
        b1, h, D_HID, NNODE, D_HID);

    // SAGE layer 2: outn = mean(h) @ W2l^T + b2 + h @ W2r^T
    k_gather<<<dim3(NNODE, D_HID / 256), 256>>>(h, aggM, D_HID);
    gemm64<false, true><<<dim3(D_NODE / 64, (NNODE + 63) / 64), 256>>>(
        aggM, D_HID, W2l, D_HID, D_HID,
        h, D_HID, W2r, D_HID, D_HID,
        b2, outn, D_NODE, NNODE, D_NODE);

    // pair pre-factors: A = attr @ Wp1[:, :512]^T + bp1 ; O = obj @ Wp1[:, 512:]^T
    gemm64<false, false><<<dim3((D_P1 + 63) / 64, (NATTR + 63) / 64), 256>>>(
        outn, D_NODE, Wp1, 2 * D_NODE, D_NODE,
        nullptr, 0, nullptr, 0, 0,
        bp1, Abuf, D_P1, NATTR, D_P1);
    gemm64<false, false><<<dim3((D_P1 + 63) / 64, (NOBJ + 63) / 64), 256>>>(
        outn + NATTR * D_NODE, D_NODE, Wp1 + D_NODE, 2 * D_NODE, D_NODE,
        nullptr, 0, nullptr, 0, 0,
        nullptr, Obuf, D_P1, NOBJ, D_P1);
    k_cvt_half<<<(NATTR * D_P1 / 4 + 255) / 256, 256>>>(Abuf, Ah, NATTR * D_P1 / 4);
    k_cvt_half<<<(NOBJ * D_P1 / 4 + 255) / 256, 256>>>(Obuf, Oh, NOBJ * D_P1 / 4);

    // image MLP
    gemm64<true, false><<<dim3(768 / 64, BIMG / 64), 256>>>(
        img, FEAT, Wi1, FEAT, FEAT,
        nullptr, 0, nullptr, 0, 0,
        bi1, i1, 768, BIMG, 768);
    gemm64<true, false><<<dim3((1000 + 63) / 64, BIMG / 64), 256>>>(
        i1, 768, Wi2, 768, 768,
        nullptr, 0, nullptr, 0, 0,
        bi2, i2, 1000, BIMG, 1000);
    gemm64<false, false><<<dim3((EMB + 63) / 64, BIMG / 64), 256>>>(
        i2, 1000, Wi3, 1000, 1000,
        nullptr, 0, nullptr, 0, 0,
        bi3, i3, EMB, BIMG, EMB);
    k_img_ln<<<BIMG, 256>>>(gi, bin_, gp, bpn);

    // big pair GEMM -> g_qh (fp16 tensor cores + ldmatrix + pipeline)
    pair_gemm<<<dim3(EMB / 80, (NPAIR + 127) / 128), 256>>>(bp2);

    // LN row stats (single pass over half q)
    k_rowstats<<<NPAIR / 8, 256>>>();

    // final fused GEMM + LN epilogue (fp16 + ldmatrix)
    k_final<<<dim3((NPAIR + 127) / 128, BIMG / 128), 256>>>(out);
}